// round 7
// baseline (speedup 1.0000x reference)
#include <cuda_runtime.h>
#include <cuda_bf16.h>
#include <cstdint>
#include <cstddef>

// Problem constants
#define BB   64          // batch
#define TT   1024        // timesteps
#define DD   512         // input dim
#define HH   512         // hidden dim
#define GG   2048        // 4*H gate dim
#define NGRP 4           // independent batch groups
#define GCTA 32          // CTAs per group
#define NB   16          // batches per group
#define NCOL 16          // hidden cols per CTA
#define LCTA 128         // lstm CTAs
#define XCTA 20          // xproj CTAs
#define NTILE 4096       // xproj tiles (256 tblocks x 16 gate-tiles)

// ---------------- device scratch ----------------
__device__ float    g_xproj[(size_t)TT * GG * BB];  // [t][gcol][b]
__device__ float    g_Wx[GG * DD];
__device__ float    g_Wh[GG * HH];
__device__ float    g_bsum[GG];
__device__ float    g_h[2][NGRP * NB * HH];         // per-group h, k-PERMUTED cols
__device__ unsigned g_bar4[NGRP * 32];              // padded barrier counters
__device__ unsigned g_wq;                           // xproj tile queue
__device__ unsigned g_done[TT / 4];                 // per-tblock finished tiles

// ---------------- helpers ----------------
__device__ __forceinline__ float tf32r(float x) {
    float y; asm("cvt.rna.tf32.f32 %0, %1;" : "=f"(y) : "f"(x)); return y;
}
__device__ __forceinline__ float tanh_fast(float x) {
    float y; asm("tanh.approx.f32 %0, %1;" : "=f"(y) : "f"(x)); return y;
}
__device__ __forceinline__ float sig_fast(float x) {
    return fmaf(tanh_fast(0.5f * x), 0.5f, 0.5f);
}
__device__ __forceinline__ void mma8(float* c,
                                     unsigned a0, unsigned a1, unsigned a2, unsigned a3,
                                     unsigned b0, unsigned b1) {
    asm volatile(
        "mma.sync.aligned.m16n8k8.row.col.f32.tf32.tf32.f32 "
        "{%0,%1,%2,%3},{%4,%5,%6,%7},{%8,%9},{%0,%1,%2,%3};\n"
        : "+f"(c[0]), "+f"(c[1]), "+f"(c[2]), "+f"(c[3])
        : "r"(a0), "r"(a1), "r"(a2), "r"(a3), "r"(b0), "r"(b1));
}
__device__ __forceinline__ void cp16(float* dst, const float* src) {
    unsigned s = (unsigned)__cvta_generic_to_shared(dst);
    asm volatile("cp.async.cg.shared.global [%0], [%1], 16;\n" :: "r"(s), "l"(src));
}
#define CP_COMMIT  asm volatile("cp.async.commit_group;\n" ::: "memory")
#define CP_WAIT(N) asm volatile("cp.async.wait_group %0;\n" :: "n"(N) : "memory")

__device__ __forceinline__ void red_release(unsigned* p) {
    asm volatile("red.release.gpu.global.add.u32 [%0], %1;" :: "l"(p), "r"(1u) : "memory");
}
__device__ __forceinline__ unsigned ld_acquire(const unsigned* p) {
    unsigned v;
    asm volatile("ld.acquire.gpu.global.u32 %0, [%1];" : "=r"(v) : "l"(p) : "memory");
    return v;
}

// k-permutation within each 8-block: true offset o -> stored offset
__device__ __host__ __forceinline__ int kperm(int o) {
    return (o < 4) ? 2 * o : 2 * (o - 4) + 1;
}

// ---------------- pack kernel ----------------
__global__ void pack_kernel(
    const float* __restrict__ Wxf, const float* __restrict__ Wxi,
    const float* __restrict__ Wxg, const float* __restrict__ Wxo,
    const float* __restrict__ Whf, const float* __restrict__ Whi,
    const float* __restrict__ Whg, const float* __restrict__ Who,
    const float* __restrict__ bxf, const float* __restrict__ bxi,
    const float* __restrict__ bxg, const float* __restrict__ bxo,
    const float* __restrict__ bhf, const float* __restrict__ bhi,
    const float* __restrict__ bhg, const float* __restrict__ bho) {
    int i = blockIdx.x * blockDim.x + threadIdx.x;
    const float* WX[4] = {Wxf, Wxi, Wxg, Wxo};
    const float* WH[4] = {Whf, Whi, Whg, Who};
    const float* BX[4] = {bxf, bxi, bxg, bxo};
    const float* BH[4] = {bhf, bhi, bhg, bho};
    const int WN = GG * DD;
    if (i < WN) {
        int row = i >> 9, col = i & 511;
        int g = row >> 9, rr = row & 511;
        g_Wx[i] = tf32r(WX[g][rr * DD + col]);
    } else if (i < 2 * WN) {
        int j = i - WN;
        int row = j >> 9, col = j & 511;
        int g = row >> 9, rr = row & 511;
        g_Wh[j] = tf32r(WH[g][rr * HH + col]);
    } else if (i < 2 * WN + GG) {
        int j = i - 2 * WN;
        int g = j >> 9, rr = j & 511;
        g_bsum[j] = BX[g][rr] + BH[g][rr];
    }
}

__global__ void init_kernel() {
    int i = blockIdx.x * blockDim.x + threadIdx.x;
    if (i < 2 * NGRP * NB * HH) ((float*)g_h)[i] = 0.0f;
    if (i < NGRP * 32) g_bar4[i] = 0u;
    if (i < TT / 4) g_done[i] = 0u;
    if (i == 0) g_wq = 0u;
}

// ---------------- xproj role: one tile (M=128 gates, N=256 = 4t x 64b, K=512) ----------------
#define XP_SMEM_FLOATS (2 * 128 * 68 + 2 * 256 * 68)   // 208896 B

__device__ void xproj_tile(float* sm, const float* __restrict__ x, int id) {
    float* sA = sm;                   // [2][128][68]
    float* sB = sm + 2 * 128 * 68;    // [2][256][68]
    const int tb = id >> 4;
    const int c0 = (id & 15) * 128;
    const int t0 = tb * 4;
    const int tid = threadIdx.x;
    const int w = tid >> 5, lane = tid & 31;
    const int wm = w & 3, wn = w >> 2;
    const int lg = lane >> 2, lt = lane & 3;

    float acc[2][16][4];
#pragma unroll
    for (int i = 0; i < 2; i++)
#pragma unroll
        for (int j = 0; j < 16; j++)
#pragma unroll
            for (int k = 0; k < 4; k++) acc[i][j][k] = 0.0f;

    auto loadA = [&](int buf, int k0) {
        float* dst = sA + buf * (128 * 68);
#pragma unroll
        for (int j = 0; j < 8; j++) {
            int l = tid + 256 * j;
            int row = l >> 4, q = l & 15;
            cp16(dst + row * 68 + q * 4, g_Wx + (size_t)(c0 + row) * DD + k0 + q * 4);
        }
    };
    auto loadB = [&](int buf, int k0) {
        float* dst = sB + buf * (256 * 68);
#pragma unroll
        for (int j = 0; j < 16; j++) {
            int l = tid + 256 * j;
            int row = l >> 4, q = l & 15;     // row = n = t'*64 + b
            int b = row & 63, tp = row >> 6;
            cp16(dst + row * 68 + q * 4,
                 x + ((size_t)b * TT + (t0 + tp)) * DD + k0 + q * 4);
        }
    };

    loadA(0, 0); loadB(0, 0); CP_COMMIT;
    for (int ch = 0; ch < 8; ch++) {
        if (ch < 7) {
            loadA((ch + 1) & 1, (ch + 1) * 64);
            loadB((ch + 1) & 1, (ch + 1) * 64);
            CP_COMMIT;
            CP_WAIT(1);
        } else {
            CP_WAIT(0);
        }
        __syncthreads();
        const float* A  = sA + (ch & 1) * (128 * 68);
        const float* Bm = sB + (ch & 1) * (256 * 68);
#pragma unroll
        for (int kk = 0; kk < 64; kk += 8) {
            unsigned a[2][4];
#pragma unroll
            for (int mi = 0; mi < 2; mi++) {
                const float* p = A + (wm * 32 + mi * 16 + lg) * 68 + kk + lt;
                a[mi][0] = __float_as_uint(p[0]);
                a[mi][1] = __float_as_uint(p[8 * 68]);
                a[mi][2] = __float_as_uint(p[4]);
                a[mi][3] = __float_as_uint(p[8 * 68 + 4]);
            }
#pragma unroll
            for (int ni = 0; ni < 16; ni++) {
                const float* p = Bm + (wn * 128 + ni * 8 + lg) * 68 + kk + lt;
                unsigned b0 = __float_as_uint(tf32r(p[0]));
                unsigned b1 = __float_as_uint(tf32r(p[4]));
                mma8(acc[0][ni], a[0][0], a[0][1], a[0][2], a[0][3], b0, b1);
                mma8(acc[1][ni], a[1][0], a[1][1], a[1][2], a[1][3], b0, b1);
            }
        }
        __syncthreads();
    }

    // epilogue: add (bx+bh), store [t][gcol][b]
#pragma unroll
    for (int mi = 0; mi < 2; mi++) {
#pragma unroll
        for (int rr = 0; rr < 2; rr++) {
            int gcol = c0 + wm * 32 + mi * 16 + rr * 8 + lg;
            float bs = g_bsum[gcol];
#pragma unroll
            for (int ni = 0; ni < 16; ni++) {
                int n = wn * 128 + ni * 8 + 2 * lt;
                int b = n & 63, tp = n >> 6;
                float2 v = make_float2(acc[mi][ni][2 * rr + 0] + bs,
                                       acc[mi][ni][2 * rr + 1] + bs);
                *(float2*)&g_xproj[(((size_t)(t0 + tp)) * GG + gcol) * BB + b] = v;
            }
        }
    }
    __syncthreads();   // all stores issued before the release below
    if (tid == 0) red_release(&g_done[tb]);
}

// ---------------- lstm role ----------------
// 128 CTAs x 256 threads. group = bid>>5 (16 batches), r = bid&31 (16 hidden cols).
// Per CTA: M = 64 gate rows, N = 16 batches, K = 512.
// Warp = (kh = w>>2 K-half, gt = w&3 gate-tile m16). Halves staged & synced independently.
#define SWHP_F4   (4 * 64 * 32)
#define SH_STRIDE 520
#define SG_STRIDE 18

__device__ void lstm_role(float* sm, float* __restrict__ out, int bid) {
    float4* sWhp = (float4*)sm;                       // A fragments [4 gt][64 q][32 lane]
    float*  sH   = sm + SWHP_F4 * 4;                  // [16][520] (k-permuted cols)
    float*  sG   = sH + NB * SH_STRIDE;               // [2][64][18]
    const int group = bid >> 5;
    const int r     = bid & 31;
    const int tid = threadIdx.x;
    const int w = tid >> 5, lane = tid & 31;
    const int lg = lane >> 2, lt = lane & 3;
    const int half = tid >> 7;          // staging half (0: cols 0-255, 1: cols 256-511)
    const int ltid = tid & 127;

    // ---- build pre-swizzled A fragments from g_Wh ----
    for (int i = tid; i < SWHP_F4; i += 256) {
        int gt = i >> 11;
        int rem = i & 2047;
        int q = rem >> 5, ln = rem & 31;
        int flg = ln >> 2, flt = ln & 3;
        int row0 = gt * 512 + r * NCOL + flg;
        int row1 = row0 + 8;
        int c0 = q * 8 + flt, c1 = c0 + 4;
        float4 v;
        v.x = g_Wh[(size_t)row0 * HH + c0];
        v.y = g_Wh[(size_t)row1 * HH + c0];
        v.z = g_Wh[(size_t)row0 * HH + c1];
        v.w = g_Wh[(size_t)row1 * HH + c1];
        sWhp[i] = v;
    }

    // cell-update ownership: 1 cell per thread
    const int jl = tid >> 4;          // local hidden col 0..15
    const int bl = tid & 15;          // local batch 0..15
    const int jglob = r * NCOL + jl;
    const int bglob = group * NB + bl;
    const int pj = (jglob & ~7) | kperm(jglob & 7);
    float cst = 0.0f;

    float4 xc, xn;
    auto ldxp = [&](int tt) {
        const float* base = g_xproj + (size_t)tt * GG * BB;
        float4 v;
        v.x = base[(size_t)(0 * 512 + jglob) * BB + bglob];
        v.y = base[(size_t)(1 * 512 + jglob) * BB + bglob];
        v.z = base[(size_t)(2 * 512 + jglob) * BB + bglob];
        v.w = base[(size_t)(3 * 512 + jglob) * BB + bglob];
        return v;
    };
    // wait for xproj tblock 0, then load step-0 xproj
    while (ld_acquire(&g_done[0]) < 16u) {}
    xc = ldxp(0);
    __syncthreads();

    const int kh = w >> 2;            // K-half
    const int gt = w & 3;             // gate-tile (m16)
    const float4* aP = sWhp + gt * 2048 + lane;
    const float* bP0 = sH + (0 * 8 + lg) * SH_STRIDE + 2 * lt;
    const float* bP1 = sH + (1 * 8 + lg) * SH_STRIDE + 2 * lt;
    const int khoff = kh * 64 * SG_STRIDE;
    unsigned* mybar = &g_bar4[group * 32];

    for (int t = 0; t < TT; t++) {
        const float* hsrc = g_h[t & 1] + (size_t)group * NB * HH;
        float*       hdst = g_h[(t & 1) ^ 1] + (size_t)group * NB * HH;

        // stage my half of h (16 rows x 256 cols f32)
#pragma unroll
        for (int j = 0; j < 8; j++) {
            int e = ltid + 128 * j;
            int row = e >> 6, q = e & 63;
            cp16(sH + row * SH_STRIDE + half * 256 + q * 4,
                 hsrc + (size_t)row * HH + half * 256 + q * 4);
        }
        CP_COMMIT;

        // prefetch next step's xproj (poll producer at tblock boundaries)
        if (t + 1 < TT) {
            int tb = (t + 1) >> 2;
            if (((t + 1) & 3) == 0) {
                while (ld_acquire(&g_done[tb]) < 16u) {}
            }
            xn = ldxp(t + 1);
        }

        CP_WAIT(0);
        // my half fully staged once all 128 threads of my half pass this barrier
        asm volatile("bar.sync %0, 128;" :: "r"(1 + half) : "memory");

        // warp MMA: m16 x n16 over K-half kh (32 k-steps)
        {
            float acc[2][4];
#pragma unroll
            for (int a = 0; a < 2; a++)
#pragma unroll
                for (int d = 0; d < 4; d++) acc[a][d] = 0.0f;

#pragma unroll 8
            for (int q = 0; q < 32; q++) {
                int kq = kh * 32 + q;
                float4 av = aP[kq * 32];
                float2 b0 = *(const float2*)(bP0 + kq * 8);
                float2 b1 = *(const float2*)(bP1 + kq * 8);
                mma8(acc[0], __float_as_uint(av.x), __float_as_uint(av.y),
                     __float_as_uint(av.z), __float_as_uint(av.w),
                     __float_as_uint(b0.x), __float_as_uint(b0.y));
                mma8(acc[1], __float_as_uint(av.x), __float_as_uint(av.y),
                     __float_as_uint(av.z), __float_as_uint(av.w),
                     __float_as_uint(b1.x), __float_as_uint(b1.y));
            }

#pragma unroll
            for (int nt = 0; nt < 2; nt++) {
                int nb0 = nt * 8 + 2 * lt;
                *(float2*)&sG[khoff + (gt * 16 + lg) * SG_STRIDE + nb0] =
                    make_float2(acc[nt][0], acc[nt][1]);
                *(float2*)&sG[khoff + (gt * 16 + lg + 8) * SG_STRIDE + nb0] =
                    make_float2(acc[nt][2], acc[nt][3]);
            }
        }
        __syncthreads();

        // cell update (1 cell per thread): merge K-halves
        {
            const int H2 = 64 * SG_STRIDE;
            float fv = sG[(0 * 16 + jl) * SG_STRIDE + bl] + sG[H2 + (0 * 16 + jl) * SG_STRIDE + bl] + xc.x;
            float iv = sG[(1 * 16 + jl) * SG_STRIDE + bl] + sG[H2 + (1 * 16 + jl) * SG_STRIDE + bl] + xc.y;
            float gv = sG[(2 * 16 + jl) * SG_STRIDE + bl] + sG[H2 + (2 * 16 + jl) * SG_STRIDE + bl] + xc.z;
            float ov = sG[(3 * 16 + jl) * SG_STRIDE + bl] + sG[H2 + (3 * 16 + jl) * SG_STRIDE + bl] + xc.w;
            float f_ = sig_fast(fv);
            float i_ = sig_fast(iv);
            float g_ = tanh_fast(gv);
            float o_ = sig_fast(ov);
            cst = f_ * cst + i_ * g_;
            float h_ = o_ * tanh_fast(cst);
            hdst[(size_t)bl * HH + pj] = tf32r(h_);
            if (t == TT - 1) out[(size_t)bglob * HH + jglob] = h_;
            xc = xn;
        }

        // group barrier: arrive once per CTA, every thread polls (no broadcast sync)
        __syncthreads();
        if (tid == 0) red_release(mybar);
        unsigned target = (unsigned)(t + 1) * GCTA;
        while (ld_acquire(mybar) < target) {}
        // each thread proceeds straight to next step's cp.async (acquire orders h reads)
    }
}

// ---------------- fused persistent kernel ----------------
__global__ void __launch_bounds__(256, 1) fused_kernel(float* __restrict__ out,
                                                       const float* __restrict__ x) {
    extern __shared__ float sm[];
    __shared__ unsigned s_tile;
    if (blockIdx.x < LCTA) {
        lstm_role(sm, out, blockIdx.x);
    } else {
        // xproj work-queue consumer
        while (true) {
            if (threadIdx.x == 0) s_tile = atomicAdd(&g_wq, 1u);
            __syncthreads();
            unsigned id = s_tile;
            if (id >= NTILE) break;
            xproj_tile(sm, x, (int)id);
            __syncthreads();
        }
    }
}

// ---------------- launcher ----------------
extern "C" void kernel_launch(void* const* d_in, const int* in_sizes, int n_in,
                              void* d_out, int out_size) {
    const float* x   = (const float*)d_in[0];
    const float* Whf = (const float*)d_in[1];  const float* bhf = (const float*)d_in[2];
    const float* Wxf = (const float*)d_in[3];  const float* bxf = (const float*)d_in[4];
    const float* Whi = (const float*)d_in[5];  const float* bhi = (const float*)d_in[6];
    const float* Wxi = (const float*)d_in[7];  const float* bxi = (const float*)d_in[8];
    const float* Whg = (const float*)d_in[9];  const float* bhg = (const float*)d_in[10];
    const float* Wxg = (const float*)d_in[11]; const float* bxg = (const float*)d_in[12];
    const float* Who = (const float*)d_in[13]; const float* bho = (const float*)d_in[14];
    const float* Wxo = (const float*)d_in[15]; const float* bxo = (const float*)d_in[16];

    const int fused_smem = XP_SMEM_FLOATS * 4;   // 208896 B (covers both roles)
    cudaFuncSetAttribute(fused_kernel, cudaFuncAttributeMaxDynamicSharedMemorySize, fused_smem);

    int packN = 2 * GG * DD + GG;
    pack_kernel<<<(packN + 255) / 256, 256>>>(Wxf, Wxi, Wxg, Wxo,
                                              Whf, Whi, Whg, Who,
                                              bxf, bxi, bxg, bxo,
                                              bhf, bhi, bhg, bho);
    init_kernel<<<(2 * NGRP * NB * HH + 255) / 256, 256>>>();

    fused_kernel<<<LCTA + XCTA, 256, fused_smem>>>((float*)d_out, x);
}

// round 11
// speedup vs baseline: 1.6548x; 1.6548x over previous
#include <cuda_runtime.h>
#include <cuda_bf16.h>
#include <cstdint>
#include <cstddef>

// Problem constants
#define BB   64          // batch
#define TT   1024        // timesteps
#define DD   512         // input dim
#define HH   512         // hidden dim
#define GG   2048        // 4*H gate dim
#define NGRP 4           // independent batch groups
#define GCTA 32          // CTAs per group
#define NB   16          // batches per group
#define NCOL 16          // hidden cols per CTA
#define LCTA 128         // lstm CTAs
#define NTILE 4096       // xproj tiles (256 tblocks x 16 gate-tiles)
#define THRESH 2560      // tiles in queue-A (consumed by all CTAs); rest by spare CTAs

// ---------------- device scratch ----------------
__device__ float    g_xproj[(size_t)TT * GG * BB];  // [t][gcol][b]
__device__ float    g_Wx[GG * DD];
__device__ float    g_Wh[GG * HH];
__device__ float    g_bsum[GG];
__device__ float    g_h[2][NGRP * NB * HH];         // per-group h, k-PERMUTED cols
__device__ unsigned g_bar4[NGRP * 32];              // padded barrier counters
__device__ unsigned g_wqA, g_wqB;                   // xproj tile queues
__device__ unsigned g_done[TT / 4];                 // per-tblock finished tiles

// ---------------- helpers ----------------
__device__ __forceinline__ float tf32r(float x) {
    float y; asm("cvt.rna.tf32.f32 %0, %1;" : "=f"(y) : "f"(x)); return y;
}
__device__ __forceinline__ float tanh_fast(float x) {
    float y; asm("tanh.approx.f32 %0, %1;" : "=f"(y) : "f"(x)); return y;
}
__device__ __forceinline__ float sig_fast(float x) {
    return fmaf(tanh_fast(0.5f * x), 0.5f, 0.5f);
}
__device__ __forceinline__ void mma8(float* c,
                                     unsigned a0, unsigned a1, unsigned a2, unsigned a3,
                                     unsigned b0, unsigned b1) {
    asm volatile(
        "mma.sync.aligned.m16n8k8.row.col.f32.tf32.tf32.f32 "
        "{%0,%1,%2,%3},{%4,%5,%6,%7},{%8,%9},{%0,%1,%2,%3};\n"
        : "+f"(c[0]), "+f"(c[1]), "+f"(c[2]), "+f"(c[3])
        : "r"(a0), "r"(a1), "r"(a2), "r"(a3), "r"(b0), "r"(b1));
}
__device__ __forceinline__ void cp16(float* dst, const float* src) {
    unsigned s = (unsigned)__cvta_generic_to_shared(dst);
    asm volatile("cp.async.cg.shared.global [%0], [%1], 16;\n" :: "r"(s), "l"(src));
}
#define CP_COMMIT  asm volatile("cp.async.commit_group;\n" ::: "memory")
#define CP_WAIT(N) asm volatile("cp.async.wait_group %0;\n" :: "n"(N) : "memory")

__device__ __forceinline__ void red_release(unsigned* p) {
    asm volatile("red.release.gpu.global.add.u32 [%0], %1;" :: "l"(p), "r"(1u) : "memory");
}
__device__ __forceinline__ unsigned ld_acquire(const unsigned* p) {
    unsigned v;
    asm volatile("ld.acquire.gpu.global.u32 %0, [%1];" : "=r"(v) : "l"(p) : "memory");
    return v;
}

// k-permutation within each 8-block: true offset o -> stored offset
__device__ __host__ __forceinline__ int kperm(int o) {
    return (o < 4) ? 2 * o : 2 * (o - 4) + 1;
}

// ---------------- pack kernel ----------------
__global__ void pack_kernel(
    const float* __restrict__ Wxf, const float* __restrict__ Wxi,
    const float* __restrict__ Wxg, const float* __restrict__ Wxo,
    const float* __restrict__ Whf, const float* __restrict__ Whi,
    const float* __restrict__ Whg, const float* __restrict__ Who,
    const float* __restrict__ bxf, const float* __restrict__ bxi,
    const float* __restrict__ bxg, const float* __restrict__ bxo,
    const float* __restrict__ bhf, const float* __restrict__ bhi,
    const float* __restrict__ bhg, const float* __restrict__ bho) {
    int i = blockIdx.x * blockDim.x + threadIdx.x;
    const float* WX[4] = {Wxf, Wxi, Wxg, Wxo};
    const float* WH[4] = {Whf, Whi, Whg, Who};
    const float* BX[4] = {bxf, bxi, bxg, bxo};
    const float* BH[4] = {bhf, bhi, bhg, bho};
    const int WN = GG * DD;
    if (i < WN) {
        int row = i >> 9, col = i & 511;
        int g = row >> 9, rr = row & 511;
        g_Wx[i] = tf32r(WX[g][rr * DD + col]);
    } else if (i < 2 * WN) {
        int j = i - WN;
        int row = j >> 9, col = j & 511;
        int g = row >> 9, rr = row & 511;
        g_Wh[j] = tf32r(WH[g][rr * HH + col]);
    } else if (i < 2 * WN + GG) {
        int j = i - 2 * WN;
        int g = j >> 9, rr = j & 511;
        g_bsum[j] = BX[g][rr] + BH[g][rr];
    }
}

__global__ void init_kernel() {
    int i = blockIdx.x * blockDim.x + threadIdx.x;
    if (i < 2 * NGRP * NB * HH) ((float*)g_h)[i] = 0.0f;
    if (i < NGRP * 32) g_bar4[i] = 0u;
    if (i < TT / 4) g_done[i] = 0u;
    if (i == 0) { g_wqA = 0u; g_wqB = (unsigned)THRESH; }
}

// ---------------- xproj role: one tile (M=128 gates, N=256 = 4t x 64b, K=512) ----------------
// B operand is used as raw fp32 bits (HW truncates to tf32; cutlass-style passthrough).
#define XP_SMEM_FLOATS (2 * 128 * 68 + 2 * 256 * 68)   // 208896 B

__device__ void xproj_tile(float* sm, const float* __restrict__ x, int id) {
    float* sA = sm;                   // [2][128][68]
    float* sB = sm + 2 * 128 * 68;    // [2][256][68]
    const int tb = id >> 4;
    const int c0 = (id & 15) * 128;
    const int t0 = tb * 4;
    const int tid = threadIdx.x;
    const int w = tid >> 5, lane = tid & 31;
    const int wm = w & 3, wn = w >> 2;
    const int lg = lane >> 2, lt = lane & 3;

    float acc[2][16][4];
#pragma unroll
    for (int i = 0; i < 2; i++)
#pragma unroll
        for (int j = 0; j < 16; j++)
#pragma unroll
            for (int k = 0; k < 4; k++) acc[i][j][k] = 0.0f;

    auto loadA = [&](int buf, int k0) {
        float* dst = sA + buf * (128 * 68);
#pragma unroll
        for (int j = 0; j < 8; j++) {
            int l = tid + 256 * j;
            int row = l >> 4, q = l & 15;
            cp16(dst + row * 68 + q * 4, g_Wx + (size_t)(c0 + row) * DD + k0 + q * 4);
        }
    };
    auto loadB = [&](int buf, int k0) {
        float* dst = sB + buf * (256 * 68);
#pragma unroll
        for (int j = 0; j < 16; j++) {
            int l = tid + 256 * j;
            int row = l >> 4, q = l & 15;     // row = n = t'*64 + b
            int b = row & 63, tp = row >> 6;
            cp16(dst + row * 68 + q * 4,
                 x + ((size_t)b * TT + (t0 + tp)) * DD + k0 + q * 4);
        }
    };

    loadA(0, 0); loadB(0, 0); CP_COMMIT;
    for (int ch = 0; ch < 8; ch++) {
        if (ch < 7) {
            loadA((ch + 1) & 1, (ch + 1) * 64);
            loadB((ch + 1) & 1, (ch + 1) * 64);
            CP_COMMIT;
            CP_WAIT(1);
        } else {
            CP_WAIT(0);
        }
        __syncthreads();
        const float* A  = sA + (ch & 1) * (128 * 68);
        const float* Bm = sB + (ch & 1) * (256 * 68);
#pragma unroll
        for (int kk = 0; kk < 64; kk += 8) {
            unsigned a[2][4];
#pragma unroll
            for (int mi = 0; mi < 2; mi++) {
                const float* p = A + (wm * 32 + mi * 16 + lg) * 68 + kk + lt;
                a[mi][0] = __float_as_uint(p[0]);
                a[mi][1] = __float_as_uint(p[8 * 68]);
                a[mi][2] = __float_as_uint(p[4]);
                a[mi][3] = __float_as_uint(p[8 * 68 + 4]);
            }
#pragma unroll
            for (int ni = 0; ni < 16; ni++) {
                const float* p = Bm + (wn * 128 + ni * 8 + lg) * 68 + kk + lt;
                unsigned b0 = __float_as_uint(p[0]);   // raw bits: HW tf32 truncation
                unsigned b1 = __float_as_uint(p[4]);
                mma8(acc[0][ni], a[0][0], a[0][1], a[0][2], a[0][3], b0, b1);
                mma8(acc[1][ni], a[1][0], a[1][1], a[1][2], a[1][3], b0, b1);
            }
        }
        __syncthreads();
    }

    // epilogue: add (bx+bh), store [t][gcol][b]
#pragma unroll
    for (int mi = 0; mi < 2; mi++) {
#pragma unroll
        for (int rr = 0; rr < 2; rr++) {
            int gcol = c0 + wm * 32 + mi * 16 + rr * 8 + lg;
            float bs = g_bsum[gcol];
#pragma unroll
            for (int ni = 0; ni < 16; ni++) {
                int n = wn * 128 + ni * 8 + 2 * lt;
                int b = n & 63, tp = n >> 6;
                float2 v = make_float2(acc[mi][ni][2 * rr + 0] + bs,
                                       acc[mi][ni][2 * rr + 1] + bs);
                *(float2*)&g_xproj[(((size_t)(t0 + tp)) * GG + gcol) * BB + b] = v;
            }
        }
    }
    __syncthreads();   // all stores issued before the release below
    if (tid == 0) red_release(&g_done[tb]);
}

// ---------------- lstm role ----------------
// 128 CTAs x 256 threads. group = bid>>5 (16 batches), r = bid&31 (16 hidden cols).
// Per CTA: M = 64 gate rows, N = 16 batches, K = 512.
// Warp = (kh = w>>2 K-half, gt = w&3 gate-tile m16). Halves staged & synced independently.
#define SWHP_F4   (4 * 64 * 32)
#define SH_STRIDE 520
#define SG_STRIDE 18

__device__ void lstm_role(float* sm, float* __restrict__ out, int bid) {
    float4* sWhp = (float4*)sm;                       // A fragments [4 gt][64 q][32 lane]
    float*  sH   = sm + SWHP_F4 * 4;                  // [16][520] (k-permuted cols)
    float*  sG   = sH + NB * SH_STRIDE;               // [2][64][18]
    const int group = bid >> 5;
    const int r     = bid & 31;
    const int tid = threadIdx.x;
    const int w = tid >> 5, lane = tid & 31;
    const int lg = lane >> 2, lt = lane & 3;
    const int half = tid >> 7;          // staging half (0: cols 0-255, 1: cols 256-511)
    const int ltid = tid & 127;

    // ---- build pre-swizzled A fragments from g_Wh ----
    for (int i = tid; i < SWHP_F4; i += 256) {
        int gt = i >> 11;
        int rem = i & 2047;
        int q = rem >> 5, ln = rem & 31;
        int flg = ln >> 2, flt = ln & 3;
        int row0 = gt * 512 + r * NCOL + flg;
        int row1 = row0 + 8;
        int c0 = q * 8 + flt, c1 = c0 + 4;
        float4 v;
        v.x = g_Wh[(size_t)row0 * HH + c0];
        v.y = g_Wh[(size_t)row1 * HH + c0];
        v.z = g_Wh[(size_t)row0 * HH + c1];
        v.w = g_Wh[(size_t)row1 * HH + c1];
        sWhp[i] = v;
    }

    // cell-update ownership: 1 cell per thread
    const int jl = tid >> 4;          // local hidden col 0..15
    const int bl = tid & 15;          // local batch 0..15
    const int jglob = r * NCOL + jl;
    const int bglob = group * NB + bl;
    const int pj = (jglob & ~7) | kperm(jglob & 7);
    float cst = 0.0f;

    float4 xc, xn;
    auto ldxp = [&](int tt) {
        const float* base = g_xproj + (size_t)tt * GG * BB;
        float4 v;
        v.x = base[(size_t)(0 * 512 + jglob) * BB + bglob];
        v.y = base[(size_t)(1 * 512 + jglob) * BB + bglob];
        v.z = base[(size_t)(2 * 512 + jglob) * BB + bglob];
        v.w = base[(size_t)(3 * 512 + jglob) * BB + bglob];
        return v;
    };
    // wait for xproj tblock 0, then load step-0 xproj
    if (tid == 0) { while (ld_acquire(&g_done[0]) < 16u) {} }
    __syncthreads();
    xc = ldxp(0);
    __syncthreads();

    const int kh = w >> 2;            // K-half
    const int gt = w & 3;             // gate-tile (m16)
    const float4* aP = sWhp + gt * 2048 + lane;
    const float* bP0 = sH + (0 * 8 + lg) * SH_STRIDE + 2 * lt;
    const float* bP1 = sH + (1 * 8 + lg) * SH_STRIDE + 2 * lt;
    const int khoff = kh * 64 * SG_STRIDE;
    unsigned* mybar = &g_bar4[group * 32];

    for (int t = 0; t < TT; t++) {
        const float* hsrc = g_h[t & 1] + (size_t)group * NB * HH;
        float*       hdst = g_h[(t & 1) ^ 1] + (size_t)group * NB * HH;

        // stage my half of h (16 rows x 256 cols f32)
#pragma unroll
        for (int j = 0; j < 8; j++) {
            int e = ltid + 128 * j;
            int row = e >> 6, q = e & 63;
            cp16(sH + row * SH_STRIDE + half * 256 + q * 4,
                 hsrc + (size_t)row * HH + half * 256 + q * 4);
        }
        CP_COMMIT;

        // prefetch next step's xproj (producer poll only at tblock boundary, tid0-gated)
        if (t + 1 < TT) {
            if (((t + 1) & 3) == 0) {
                int tb = (t + 1) >> 2;
                if (tid == 0) { while (ld_acquire(&g_done[tb]) < 16u) {} }
                __syncthreads();
            }
            xn = ldxp(t + 1);
        }

        CP_WAIT(0);
        // my half fully staged once all 128 threads of my half pass this barrier
        asm volatile("bar.sync %0, 128;" :: "r"(1 + half) : "memory");

        // warp MMA: m16 x n16 over K-half kh (32 k-steps)
        {
            float acc[2][4];
#pragma unroll
            for (int a = 0; a < 2; a++)
#pragma unroll
                for (int d = 0; d < 4; d++) acc[a][d] = 0.0f;

#pragma unroll 8
            for (int q = 0; q < 32; q++) {
                int kq = kh * 32 + q;
                float4 av = aP[kq * 32];
                float2 b0 = *(const float2*)(bP0 + kq * 8);
                float2 b1 = *(const float2*)(bP1 + kq * 8);
                mma8(acc[0], __float_as_uint(av.x), __float_as_uint(av.y),
                     __float_as_uint(av.z), __float_as_uint(av.w),
                     __float_as_uint(b0.x), __float_as_uint(b0.y));
                mma8(acc[1], __float_as_uint(av.x), __float_as_uint(av.y),
                     __float_as_uint(av.z), __float_as_uint(av.w),
                     __float_as_uint(b1.x), __float_as_uint(b1.y));
            }

#pragma unroll
            for (int nt = 0; nt < 2; nt++) {
                int nb0 = nt * 8 + 2 * lt;
                *(float2*)&sG[khoff + (gt * 16 + lg) * SG_STRIDE + nb0] =
                    make_float2(acc[nt][0], acc[nt][1]);
                *(float2*)&sG[khoff + (gt * 16 + lg + 8) * SG_STRIDE + nb0] =
                    make_float2(acc[nt][2], acc[nt][3]);
            }
        }
        __syncthreads();

        // cell update (1 cell per thread): merge K-halves
        {
            const int H2 = 64 * SG_STRIDE;
            float fv = sG[(0 * 16 + jl) * SG_STRIDE + bl] + sG[H2 + (0 * 16 + jl) * SG_STRIDE + bl] + xc.x;
            float iv = sG[(1 * 16 + jl) * SG_STRIDE + bl] + sG[H2 + (1 * 16 + jl) * SG_STRIDE + bl] + xc.y;
            float gv = sG[(2 * 16 + jl) * SG_STRIDE + bl] + sG[H2 + (2 * 16 + jl) * SG_STRIDE + bl] + xc.z;
            float ov = sG[(3 * 16 + jl) * SG_STRIDE + bl] + sG[H2 + (3 * 16 + jl) * SG_STRIDE + bl] + xc.w;
            float f_ = sig_fast(fv);
            float i_ = sig_fast(iv);
            float g_ = tanh_fast(gv);
            float o_ = sig_fast(ov);
            cst = f_ * cst + i_ * g_;
            float h_ = o_ * tanh_fast(cst);
            hdst[(size_t)bl * HH + pj] = tf32r(h_);
            if (t == TT - 1) out[(size_t)bglob * HH + jglob] = h_;
            xc = xn;
        }

        // group barrier: tid0 arrives + polls, CTA-wide broadcast via syncthreads
        __syncthreads();
        if (tid == 0) {
            red_release(mybar);
            unsigned target = (unsigned)(t + 1) * GCTA;
            while (ld_acquire(mybar) < target) {}
        }
        __syncthreads();
    }
}

// ---------------- fused persistent kernel ----------------
__global__ void __launch_bounds__(256, 1) fused_kernel(float* __restrict__ out,
                                                       const float* __restrict__ x) {
    extern __shared__ float sm[];
    __shared__ unsigned s_tile;
    // Phase A: all CTAs drain queue-A (tiles 0..THRESH)
    while (true) {
        if (threadIdx.x == 0) s_tile = atomicAdd(&g_wqA, 1u);
        __syncthreads();
        unsigned id = s_tile;
        if (id >= THRESH) break;
        xproj_tile(sm, x, (int)id);
        __syncthreads();
    }
    __syncthreads();

    if (blockIdx.x < LCTA) {
        lstm_role(sm, out, blockIdx.x);
    } else {
        // Phase B: spare CTAs drain queue-B (tiles THRESH..NTILE)
        while (true) {
            if (threadIdx.x == 0) s_tile = atomicAdd(&g_wqB, 1u);
            __syncthreads();
            unsigned id = s_tile;
            if (id >= NTILE) break;
            xproj_tile(sm, x, (int)id);
            __syncthreads();
        }
    }
}

// ---------------- launcher ----------------
extern "C" void kernel_launch(void* const* d_in, const int* in_sizes, int n_in,
                              void* d_out, int out_size) {
    const float* x   = (const float*)d_in[0];
    const float* Whf = (const float*)d_in[1];  const float* bhf = (const float*)d_in[2];
    const float* Wxf = (const float*)d_in[3];  const float* bxf = (const float*)d_in[4];
    const float* Whi = (const float*)d_in[5];  const float* bhi = (const float*)d_in[6];
    const float* Wxi = (const float*)d_in[7];  const float* bxi = (const float*)d_in[8];
    const float* Whg = (const float*)d_in[9];  const float* bhg = (const float*)d_in[10];
    const float* Wxg = (const float*)d_in[11]; const float* bxg = (const float*)d_in[12];
    const float* Who = (const float*)d_in[13]; const float* bho = (const float*)d_in[14];
    const float* Wxo = (const float*)d_in[15]; const float* bxo = (const float*)d_in[16];

    const int fused_smem = XP_SMEM_FLOATS * 4;   // 208896 B (covers both roles)
    cudaFuncSetAttribute(fused_kernel, cudaFuncAttributeMaxDynamicSharedMemorySize, fused_smem);

    int packN = 2 * GG * DD + GG;
    pack_kernel<<<(packN + 255) / 256, 256>>>(Wxf, Wxi, Wxg, Wxo,
                                              Whf, Whi, Whg, Who,
                                              bxf, bxi, bxg, bxo,
                                              bhf, bhi, bhg, bho);
    init_kernel<<<(2 * NGRP * NB * HH + 255) / 256, 256>>>();

    fused_kernel<<<148, 256, fused_smem>>>((float*)d_out, x);
}

// round 12
// speedup vs baseline: 1.7941x; 1.0841x over previous
#include <cuda_runtime.h>
#include <cuda_bf16.h>
#include <cstdint>
#include <cstddef>

// Problem constants
#define BB   64          // batch
#define TT   1024        // timesteps
#define DD   512         // input dim
#define HH   512         // hidden dim
#define GG   2048        // 4*H gate dim
#define NGRP 4           // independent batch groups
#define GCTA 32          // CTAs per group
#define NB   16          // batches per group
#define NCOL 16          // hidden cols per CTA
#define LCTA 128         // lstm CTAs
#define NTILE 4096       // xproj tiles (256 tblocks x 16 gate-tiles)
#define THRESH 3072      // tiles in queue-A (all CTAs); rest by spare CTAs

// ---------------- device scratch ----------------
__device__ float    g_xproj[(size_t)TT * GG * BB];  // [t][gcol][b]
__device__ float    g_Wx[GG * DD];
__device__ float    g_Wh[GG * HH];
__device__ float    g_bsum[GG];
__device__ float    g_h[2][NGRP * NB * HH];         // per-group h, k-PERMUTED cols
__device__ unsigned g_bar4[NGRP * 32];              // padded barrier counters
__device__ unsigned g_wqA, g_wqB;                   // xproj tile queues
__device__ unsigned g_done[TT / 4];                 // per-tblock finished tiles

// ---------------- helpers ----------------
__device__ __forceinline__ float tf32r(float x) {
    float y; asm("cvt.rna.tf32.f32 %0, %1;" : "=f"(y) : "f"(x)); return y;
}
__device__ __forceinline__ float tanh_fast(float x) {
    float y; asm("tanh.approx.f32 %0, %1;" : "=f"(y) : "f"(x)); return y;
}
__device__ __forceinline__ float sig_fast(float x) {
    return fmaf(tanh_fast(0.5f * x), 0.5f, 0.5f);
}
__device__ __forceinline__ void mma8(float* c,
                                     unsigned a0, unsigned a1, unsigned a2, unsigned a3,
                                     unsigned b0, unsigned b1) {
    asm volatile(
        "mma.sync.aligned.m16n8k8.row.col.f32.tf32.tf32.f32 "
        "{%0,%1,%2,%3},{%4,%5,%6,%7},{%8,%9},{%0,%1,%2,%3};\n"
        : "+f"(c[0]), "+f"(c[1]), "+f"(c[2]), "+f"(c[3])
        : "r"(a0), "r"(a1), "r"(a2), "r"(a3), "r"(b0), "r"(b1));
}
__device__ __forceinline__ void mma8f(float* c, const float4& av, float2 b) {
    mma8(c, __float_as_uint(av.x), __float_as_uint(av.y),
         __float_as_uint(av.z), __float_as_uint(av.w),
         __float_as_uint(b.x), __float_as_uint(b.y));
}
__device__ __forceinline__ void cp16(float* dst, const float* src) {
    unsigned s = (unsigned)__cvta_generic_to_shared(dst);
    asm volatile("cp.async.cg.shared.global [%0], [%1], 16;\n" :: "r"(s), "l"(src));
}
#define CP_COMMIT  asm volatile("cp.async.commit_group;\n" ::: "memory")
#define CP_WAIT(N) asm volatile("cp.async.wait_group %0;\n" :: "n"(N) : "memory")

__device__ __forceinline__ void red_release(unsigned* p) {
    asm volatile("red.release.gpu.global.add.u32 [%0], %1;" :: "l"(p), "r"(1u) : "memory");
}
__device__ __forceinline__ unsigned ld_acquire(const unsigned* p) {
    unsigned v;
    asm volatile("ld.acquire.gpu.global.u32 %0, [%1];" : "=r"(v) : "l"(p) : "memory");
    return v;
}

// k-permutation within each 8-block: true offset o -> stored offset
__device__ __host__ __forceinline__ int kperm(int o) {
    return (o < 4) ? 2 * o : 2 * (o - 4) + 1;
}

// ---------------- pack kernel ----------------
__global__ void pack_kernel(
    const float* __restrict__ Wxf, const float* __restrict__ Wxi,
    const float* __restrict__ Wxg, const float* __restrict__ Wxo,
    const float* __restrict__ Whf, const float* __restrict__ Whi,
    const float* __restrict__ Whg, const float* __restrict__ Who,
    const float* __restrict__ bxf, const float* __restrict__ bxi,
    const float* __restrict__ bxg, const float* __restrict__ bxo,
    const float* __restrict__ bhf, const float* __restrict__ bhi,
    const float* __restrict__ bhg, const float* __restrict__ bho) {
    int i = blockIdx.x * blockDim.x + threadIdx.x;
    const float* WX[4] = {Wxf, Wxi, Wxg, Wxo};
    const float* WH[4] = {Whf, Whi, Whg, Who};
    const float* BX[4] = {bxf, bxi, bxg, bxo};
    const float* BH[4] = {bhf, bhi, bhg, bho};
    const int WN = GG * DD;
    if (i < WN) {
        int row = i >> 9, col = i & 511;
        int g = row >> 9, rr = row & 511;
        g_Wx[i] = tf32r(WX[g][rr * DD + col]);
    } else if (i < 2 * WN) {
        int j = i - WN;
        int row = j >> 9, col = j & 511;
        int g = row >> 9, rr = row & 511;
        g_Wh[j] = tf32r(WH[g][rr * HH + col]);
    } else if (i < 2 * WN + GG) {
        int j = i - 2 * WN;
        int g = j >> 9, rr = j & 511;
        g_bsum[j] = BX[g][rr] + BH[g][rr];
    }
}

__global__ void init_kernel() {
    int i = blockIdx.x * blockDim.x + threadIdx.x;
    if (i < 2 * NGRP * NB * HH) ((float*)g_h)[i] = 0.0f;
    if (i < NGRP * 32) g_bar4[i] = 0u;
    if (i < TT / 4) g_done[i] = 0u;
    if (i == 0) { g_wqA = 0u; g_wqB = (unsigned)THRESH; }
}

// ---------------- xproj role (512 threads): one tile M=128, N=256 (4t x 64b), K=512 ----------------
// 16 warps: wm = w&3 (m32), wn = w>>2 (n64). B used as raw fp32 bits (HW tf32 truncation).
#define XP_SMEM_FLOATS (2 * 128 * 68 + 2 * 256 * 68)   // 208896 B

__device__ void xproj_tile(float* sm, const float* __restrict__ x, int id) {
    float* sA = sm;                   // [2][128][68]
    float* sB = sm + 2 * 128 * 68;    // [2][256][68]
    const int tb = id >> 4;
    const int c0 = (id & 15) * 128;
    const int t0 = tb * 4;
    const int tid = threadIdx.x;
    const int w = tid >> 5, lane = tid & 31;
    const int wm = w & 3, wn = w >> 2;
    const int lg = lane >> 2, lt = lane & 3;

    float acc[2][8][4];
#pragma unroll
    for (int i = 0; i < 2; i++)
#pragma unroll
        for (int j = 0; j < 8; j++)
#pragma unroll
            for (int k = 0; k < 4; k++) acc[i][j][k] = 0.0f;

    auto loadA = [&](int buf, int k0) {
        float* dst = sA + buf * (128 * 68);
#pragma unroll
        for (int j = 0; j < 4; j++) {
            int l = tid + 512 * j;
            int row = l >> 4, q = l & 15;
            cp16(dst + row * 68 + q * 4, g_Wx + (size_t)(c0 + row) * DD + k0 + q * 4);
        }
    };
    auto loadB = [&](int buf, int k0) {
        float* dst = sB + buf * (256 * 68);
#pragma unroll
        for (int j = 0; j < 8; j++) {
            int l = tid + 512 * j;
            int row = l >> 4, q = l & 15;     // row = n = t'*64 + b
            int b = row & 63, tp = row >> 6;
            cp16(dst + row * 68 + q * 4,
                 x + ((size_t)b * TT + (t0 + tp)) * DD + k0 + q * 4);
        }
    };

    loadA(0, 0); loadB(0, 0); CP_COMMIT;
    for (int ch = 0; ch < 8; ch++) {
        if (ch < 7) {
            loadA((ch + 1) & 1, (ch + 1) * 64);
            loadB((ch + 1) & 1, (ch + 1) * 64);
            CP_COMMIT;
            CP_WAIT(1);
        } else {
            CP_WAIT(0);
        }
        __syncthreads();
        const float* A  = sA + (ch & 1) * (128 * 68);
        const float* Bm = sB + (ch & 1) * (256 * 68);
#pragma unroll
        for (int kk = 0; kk < 64; kk += 8) {
            unsigned a[2][4];
#pragma unroll
            for (int mi = 0; mi < 2; mi++) {
                const float* p = A + (wm * 32 + mi * 16 + lg) * 68 + kk + lt;
                a[mi][0] = __float_as_uint(p[0]);
                a[mi][1] = __float_as_uint(p[8 * 68]);
                a[mi][2] = __float_as_uint(p[4]);
                a[mi][3] = __float_as_uint(p[8 * 68 + 4]);
            }
#pragma unroll
            for (int ni = 0; ni < 8; ni++) {
                const float* p = Bm + (wn * 64 + ni * 8 + lg) * 68 + kk + lt;
                unsigned b0 = __float_as_uint(p[0]);   // raw bits
                unsigned b1 = __float_as_uint(p[4]);
                mma8(acc[0][ni], a[0][0], a[0][1], a[0][2], a[0][3], b0, b1);
                mma8(acc[1][ni], a[1][0], a[1][1], a[1][2], a[1][3], b0, b1);
            }
        }
        __syncthreads();
    }

    // epilogue: add (bx+bh), store [t][gcol][b]
#pragma unroll
    for (int mi = 0; mi < 2; mi++) {
#pragma unroll
        for (int rr = 0; rr < 2; rr++) {
            int gcol = c0 + wm * 32 + mi * 16 + rr * 8 + lg;
            float bs = g_bsum[gcol];
#pragma unroll
            for (int ni = 0; ni < 8; ni++) {
                int n = wn * 64 + ni * 8 + 2 * lt;
                int b = n & 63, tp = n >> 6;
                float2 v = make_float2(acc[mi][ni][2 * rr + 0] + bs,
                                       acc[mi][ni][2 * rr + 1] + bs);
                *(float2*)&g_xproj[(((size_t)(t0 + tp)) * GG + gcol) * BB + b] = v;
            }
        }
    }
    __syncthreads();   // all stores issued before the release below
    if (tid == 0) red_release(&g_done[tb]);
}

// ---------------- lstm role (512 threads, Wh in REGISTERS) ----------------
// 128 CTAs. group = bid>>5 (16 batches), r = bid&31 (16 hidden cols).
// Per CTA: M = 64 gate rows (4 gates x 16 cols), N = 16 batches, K = 512.
// 16 warps: gt = w&3 (gate m16), kq = w>>2 (K-quarter 128).
// A fragments held in 64 registers/lane, loaded once. Staging halves by tid>>8.
#define SH_STRIDE 520
#define SG_STRIDE 18
#define LSTM_SMEM_FLOATS (NB * SH_STRIDE + 4 * 64 * SG_STRIDE)

__device__ void lstm_role(float* sm, float* __restrict__ out, int bid) {
    float* sH = sm;                        // [16][520] (k-permuted cols)
    float* sG = sm + NB * SH_STRIDE;       // [4 kq][64][18]
    const int group = bid >> 5;
    const int r     = bid & 31;
    const int tid = threadIdx.x;
    const int w = tid >> 5, lane = tid & 31;
    const int lg = lane >> 2, lt = lane & 3;
    const int gt = w & 3;                  // gate index (m16 tile)
    const int kq = w >> 2;                 // K-quarter
    const int half = tid >> 8;             // staging half (cols 0-255 / 256-511)
    const int ltid = tid & 255;

    // ---- load my A fragments (Wh, tf32-rounded) into registers: 16 float4 ----
    float4 av[16];
    {
        const int row0 = gt * 512 + r * NCOL + lg;
        const int row1 = row0 + 8;
#pragma unroll
        for (int q = 0; q < 16; q++) {
            int cc0 = kq * 128 + q * 8 + lt, cc1 = cc0 + 4;
            av[q].x = g_Wh[(size_t)row0 * HH + cc0];
            av[q].y = g_Wh[(size_t)row1 * HH + cc0];
            av[q].z = g_Wh[(size_t)row0 * HH + cc1];
            av[q].w = g_Wh[(size_t)row1 * HH + cc1];
        }
    }

    // cell-update ownership (threads 0-255): 1 cell per thread
    const int jl = (tid >> 4) & 15;
    const int bl = tid & 15;
    const int jglob = r * NCOL + jl;
    const int bglob = group * NB + bl;
    const int pj = (jglob & ~7) | kperm(jglob & 7);
    float cst = 0.0f;

    float4 xc = make_float4(0.f, 0.f, 0.f, 0.f), xn = xc;
    auto ldxp = [&](int tt) {
        const float* base = g_xproj + (size_t)tt * GG * BB;
        float4 v;
        v.x = base[(size_t)(0 * 512 + jglob) * BB + bglob];
        v.y = base[(size_t)(1 * 512 + jglob) * BB + bglob];
        v.z = base[(size_t)(2 * 512 + jglob) * BB + bglob];
        v.w = base[(size_t)(3 * 512 + jglob) * BB + bglob];
        return v;
    };
    // wait for xproj tblock 0, then load step-0 xproj
    if (tid == 0) { while (ld_acquire(&g_done[0]) < 16u) {} }
    __syncthreads();
    if (tid < 256) xc = ldxp(0);
    __syncthreads();

    const float* bP0 = sH + (0 + lg) * SH_STRIDE + kq * 128 + 2 * lt;
    const float* bP1 = sH + (8 + lg) * SH_STRIDE + kq * 128 + 2 * lt;
    float* sGq = sG + kq * 64 * SG_STRIDE;
    unsigned* mybar = &g_bar4[group * 32];

    for (int t = 0; t < TT; t++) {
        const float* hsrc = g_h[t & 1] + (size_t)group * NB * HH;
        float*       hdst = g_h[(t & 1) ^ 1] + (size_t)group * NB * HH;

        // stage my half of h (16 rows x 256 cols f32): 4 cp16/thread
#pragma unroll
        for (int j = 0; j < 4; j++) {
            int e = ltid + 256 * j;
            int row = e >> 6, q = e & 63;
            cp16(sH + row * SH_STRIDE + half * 256 + q * 4,
                 hsrc + (size_t)row * HH + half * 256 + q * 4);
        }
        CP_COMMIT;

        // prefetch next step's xproj (producer poll only at tblock boundary)
        if (t + 1 < TT) {
            if (((t + 1) & 3) == 0) {
                int tb = (t + 1) >> 2;
                if (tid == 0) { while (ld_acquire(&g_done[tb]) < 16u) {} }
                __syncthreads();
            }
            if (tid < 256) xn = ldxp(t + 1);
        }

        CP_WAIT(0);
        // my half fully staged once all 256 threads of my half pass this barrier
        asm volatile("bar.sync %0, 256;" :: "r"(1 + half) : "memory");

        // warp MMA: m16 x n16 over K-quarter kq (16 k-steps), A in registers
        {
            float acc[2][4];
#pragma unroll
            for (int a = 0; a < 2; a++)
#pragma unroll
                for (int d = 0; d < 4; d++) acc[a][d] = 0.0f;

#pragma unroll
            for (int q = 0; q < 16; q++) {
                float2 b0 = *(const float2*)(bP0 + q * 8);
                float2 b1 = *(const float2*)(bP1 + q * 8);
                mma8f(acc[0], av[q], b0);
                mma8f(acc[1], av[q], b1);
            }

#pragma unroll
            for (int nt = 0; nt < 2; nt++) {
                int nb0 = nt * 8 + 2 * lt;
                *(float2*)&sGq[(gt * 16 + lg) * SG_STRIDE + nb0] =
                    make_float2(acc[nt][0], acc[nt][1]);
                *(float2*)&sGq[(gt * 16 + lg + 8) * SG_STRIDE + nb0] =
                    make_float2(acc[nt][2], acc[nt][3]);
            }
        }
        __syncthreads();

        // cell update (threads 0-255, 1 cell each): merge 4 K-quarters
        if (tid < 256) {
            const int Q = 64 * SG_STRIDE;
            float fv = xc.x, iv = xc.y, gv = xc.z, ov = xc.w;
#pragma unroll
            for (int qq = 0; qq < 4; qq++) {
                fv += sG[qq * Q + (0 * 16 + jl) * SG_STRIDE + bl];
                iv += sG[qq * Q + (1 * 16 + jl) * SG_STRIDE + bl];
                gv += sG[qq * Q + (2 * 16 + jl) * SG_STRIDE + bl];
                ov += sG[qq * Q + (3 * 16 + jl) * SG_STRIDE + bl];
            }
            float f_ = sig_fast(fv);
            float i_ = sig_fast(iv);
            float g_ = tanh_fast(gv);
            float o_ = sig_fast(ov);
            cst = f_ * cst + i_ * g_;
            float h_ = o_ * tanh_fast(cst);
            hdst[(size_t)bl * HH + pj] = tf32r(h_);
            if (t == TT - 1) out[(size_t)bglob * HH + jglob] = h_;
            xc = xn;
        }

        // group barrier: tid0 arrives + polls, CTA-wide broadcast via syncthreads
        __syncthreads();
        if (tid == 0) {
            red_release(mybar);
            unsigned target = (unsigned)(t + 1) * GCTA;
            while (ld_acquire(mybar) < target) {}
        }
        __syncthreads();
    }
}

// ---------------- fused persistent kernel ----------------
__global__ void __launch_bounds__(512, 1) fused_kernel(float* __restrict__ out,
                                                       const float* __restrict__ x) {
    extern __shared__ float sm[];
    __shared__ unsigned s_tile;
    // Phase A: all CTAs drain queue-A (tiles 0..THRESH)
    while (true) {
        if (threadIdx.x == 0) s_tile = atomicAdd(&g_wqA, 1u);
        __syncthreads();
        unsigned id = s_tile;
        if (id >= THRESH) break;
        xproj_tile(sm, x, (int)id);
        __syncthreads();
    }
    __syncthreads();

    if (blockIdx.x < LCTA) {
        lstm_role(sm, out, blockIdx.x);
    } else {
        // Phase B: spare CTAs drain queue-B (tiles THRESH..NTILE)
        while (true) {
            if (threadIdx.x == 0) s_tile = atomicAdd(&g_wqB, 1u);
            __syncthreads();
            unsigned id = s_tile;
            if (id >= NTILE) break;
            xproj_tile(sm, x, (int)id);
            __syncthreads();
        }
    }
}

// ---------------- launcher ----------------
extern "C" void kernel_launch(void* const* d_in, const int* in_sizes, int n_in,
                              void* d_out, int out_size) {
    const float* x   = (const float*)d_in[0];
    const float* Whf = (const float*)d_in[1];  const float* bhf = (const float*)d_in[2];
    const float* Wxf = (const float*)d_in[3];  const float* bxf = (const float*)d_in[4];
    const float* Whi = (const float*)d_in[5];  const float* bhi = (const float*)d_in[6];
    const float* Wxi = (const float*)d_in[7];  const float* bxi = (const float*)d_in[8];
    const float* Whg = (const float*)d_in[9];  const float* bhg = (const float*)d_in[10];
    const float* Wxg = (const float*)d_in[11]; const float* bxg = (const float*)d_in[12];
    const float* Who = (const float*)d_in[13]; const float* bho = (const float*)d_in[14];
    const float* Wxo = (const float*)d_in[15]; const float* bxo = (const float*)d_in[16];

    const int fused_smem = XP_SMEM_FLOATS * 4;   // 208896 B (covers both roles)
    cudaFuncSetAttribute(fused_kernel, cudaFuncAttributeMaxDynamicSharedMemorySize, fused_smem);

    int packN = 2 * GG * DD + GG;
    pack_kernel<<<(packN + 255) / 256, 256>>>(Wxf, Wxi, Wxg, Wxo,
                                              Whf, Whi, Whg, Who,
                                              bxf, bxi, bxg, bxo,
                                              bhf, bhi, bhg, bho);
    init_kernel<<<(2 * NGRP * NB * HH + 255) / 256, 256>>>();

    fused_kernel<<<148, 512, fused_smem>>>((float*)d_out, x);
}